// round 14
// baseline (speedup 1.0000x reference)
#include <cuda_runtime.h>
#include <cuda_fp16.h>
#include <cstdint>

#define NPT   120000
#define HID   128
#define INP   320
#define CINL  448
#define KOFF  28
#define KTOT  (KOFF * CINL)     // 12544

// ---------------- device scratch ----------------
__device__ __half g_HX [(size_t)NPT * CINL];
__device__ __half g_RX [(size_t)NPT * CINL];
__device__ float  g_Z  [(size_t)NPT * HID];
__device__ __half g_Wzr[(size_t)256 * KTOT];   // [n][k*448+c]  n<128: z, n>=128: r
__device__ __half g_Wq [(size_t)128 * KTOT];   // [n][k*448+c]
// G buffer, PERMUTED column layout within each 32-col warp chunk:
//   storage half index within chunk = tg*8 + nt*2 + e  (chunk w at halves w*32)
__device__ __half g_G  [(size_t)KOFF * NPT * 256];
__device__ int    g_list[(size_t)27 * NPT];
__device__ int    g_cnt[27];
// persistent-CTA work lists: (kk<<16)|tile
__device__ int    g_wk1[(size_t)KOFF * ((NPT + 127) / 128)];
__device__ int    g_wk2[(size_t)KOFF * ((NPT + 255) / 256)];
__device__ int    g_nwork[2];
__device__ int    g_work[2];

// ---------------- asm helpers ----------------
__device__ __forceinline__ uint32_t smem_u32(const void* p) {
    uint32_t a;
    asm("{ .reg .u64 t; cvta.to.shared.u64 t, %1; cvt.u32.u64 %0, t; }" : "=r"(a) : "l"(p));
    return a;
}
__device__ __forceinline__ void cp16(uint32_t dst, const void* src, int sz) {
    asm volatile("cp.async.cg.shared.global [%0], [%1], 16, %2;"
                 :: "r"(dst), "l"(src), "r"(sz) : "memory");
}
#define CP_COMMIT() asm volatile("cp.async.commit_group;" ::: "memory")
#define CP_WAIT2()  asm volatile("cp.async.wait_group 2;" ::: "memory")

#define LDSM_X4(r0, r1, r2, r3, addr) \
    asm volatile("ldmatrix.sync.aligned.m8n8.x4.shared.b16 {%0,%1,%2,%3}, [%4];" \
        : "=r"(r0), "=r"(r1), "=r"(r2), "=r"(r3) : "r"(addr))

__device__ __forceinline__ void mma16816(float* d, const uint32_t* a, uint32_t b0, uint32_t b1) {
    asm volatile(
        "mma.sync.aligned.m16n8k16.row.col.f32.f16.f16.f32 "
        "{%0,%1,%2,%3}, {%4,%5,%6,%7}, {%8,%9}, {%0,%1,%2,%3};"
        : "+f"(d[0]), "+f"(d[1]), "+f"(d[2]), "+f"(d[3])
        : "r"(a[0]), "r"(a[1]), "r"(a[2]), "r"(a[3]), "r"(b0), "r"(b1));
}

// ---------------- small kernels ----------------
__global__ void pack_inputs(const float* __restrict__ h, const float* __restrict__ x, int N) {
    if (blockIdx.x == 0 && threadIdx.x < 27) g_cnt[threadIdx.x] = 0;
    size_t idx = (size_t)blockIdx.x * blockDim.x + threadIdx.x;
    size_t total = (size_t)N * CINL;
    if (idx >= total) return;
    int c = (int)(idx % CINL);
    size_t n = idx / CINL;
    float v = (c < HID) ? h[n * HID + c] : x[n * INP + (c - HID)];
    __half hv = __float2half_rn(v);
    g_HX[idx] = hv;
    if (c >= HID) g_RX[idx] = hv;
}

__global__ void pack_wzr(const float* __restrict__ Wz, const float* __restrict__ Wz_pt,
                         const float* __restrict__ Wr, const float* __restrict__ Wr_pt) {
    size_t idx = (size_t)blockIdx.x * blockDim.x + threadIdx.x;
    size_t total = (size_t)256 * KTOT;
    if (idx >= total) return;
    int rem = (int)(idx % KTOT);
    int n = (int)(idx / KTOT);
    int k = rem / CINL;
    int c = rem % CINL;
    float v;
    if (n < HID) v = (k < 27) ? Wz[((size_t)k * CINL + c) * HID + n] : Wz_pt[(size_t)c * HID + n];
    else {
        int m = n - HID;
        v = (k < 27) ? Wr[((size_t)k * CINL + c) * HID + m] : Wr_pt[(size_t)c * HID + m];
    }
    g_Wzr[idx] = __float2half_rn(v);
}

__global__ void pack_wq(const float* __restrict__ Wq, const float* __restrict__ Wq_pt) {
    size_t idx = (size_t)blockIdx.x * blockDim.x + threadIdx.x;
    size_t total = (size_t)128 * KTOT;
    if (idx >= total) return;
    int rem = (int)(idx % KTOT);
    int n = (int)(idx / KTOT);
    int k = rem / CINL;
    int c = rem % CINL;
    float v = (k < 27) ? Wq[((size_t)k * CINL + c) * HID + n] : Wq_pt[(size_t)c * HID + n];
    g_Wq[idx] = __float2half_rn(v);
}

// build per-k lists of rows j that are read as k-neighbors:
// G[k][j] is needed  <=>  nbr[j][26-k] >= 0   (mirror symmetry)
__global__ void build_lists(const int* __restrict__ nbr, int N) {
    const int j = blockIdx.x * blockDim.x + threadIdx.x;
    const int lane = threadIdx.x & 31;
    const bool inb = (j < N);
#pragma unroll 1
    for (int k = 0; k < 27; ++k) {
        bool v = inb && (nbr[(size_t)j * 27 + (26 - k)] >= 0);
        unsigned m = __ballot_sync(0xffffffffu, v);
        int base = 0;
        if (lane == 0 && m) base = atomicAdd(&g_cnt[k], __popc(m));
        base = __shfl_sync(0xffffffffu, base, 0);
        if (v) g_list[(size_t)k * NPT + base + __popc(m & ((1u << lane) - 1u))] = j;
    }
}

// build dense work lists for persistent GEMMs; reset counters (graph-safe)
__global__ void make_work(int N) {
    __shared__ int off1[KOFF + 1], off2[KOFF + 1];
    const int tid = threadIdx.x;
    if (tid == 0) {
        int n1 = 0, n2 = 0;
        for (int k = 0; k < KOFF; ++k) {
            off1[k] = n1; off2[k] = n2;
            const int cnt = (k < 27) ? g_cnt[k] : N;
            n1 += (cnt + 127) / 128;
            n2 += (cnt + 255) / 256;
        }
        off1[KOFF] = n1; off2[KOFF] = n2;
        g_nwork[0] = n1; g_nwork[1] = n2;
        g_work[0] = 0;   g_work[1] = 0;
    }
    __syncthreads();
    if (tid < KOFF) {
        const int k = tid;
        const int cnt = (k < 27) ? g_cnt[k] : N;
        int o = off1[k];
        for (int t = 0; t * 128 < cnt; ++t) g_wk1[o++] = (k << 16) | t;
        o = off2[k];
        for (int t = 0; t * 256 < cnt; ++t) g_wk2[o++] = (k << 16) | t;
    }
}

// ---------------- persistent G GEMM kernel ----------------
//   PASS 1: G[k][j][0:256] = HX[j] @ Wzr[k]   BM=128 (WM=2) x BN=256 (WN=8)
//   PASS 2: G[k][j][0:128] = RX[j] @ Wq[k]    BM=256 (WM=4) x BN=128 (WN=4)
// Work-stealing: grid = #SMs; each CTA loops over dense (k,tile) work items.
template <int PASS, int WM, int WN>
__global__ void __launch_bounds__(512, 1)
gemm_G(int N) {
    constexpr int BM = WM * 64;
    constexpr int BN = WN * 32;
    constexpr int A_BY = BM * 128;
    constexpr int B_BY = BN * 128;
    constexpr int STG = A_BY + B_BY;          // 49152 both
    constexpr int GCOLS = (PASS == 1) ? 256 : 128;
    constexpr int P = (PASS == 1) ? 0 : 1;

    extern __shared__ __align__(128) char dynsmem[];
    __shared__ int sh_wi;

    const int tid  = threadIdx.x;
    const int wid  = tid >> 5;
    const int lane = tid & 31;
    const int wm   = wid / WN;
    const int wn   = wid % WN;
    const int grp  = lane >> 2;
    const int tg   = lane & 3;

    const __half* __restrict__ Asrc = (PASS == 1) ? g_HX : g_RX;
    const __half* __restrict__ WB   = (PASS == 1) ? g_Wzr : g_Wq;
    const int* __restrict__ wk = (PASS == 1) ? g_wk1 : g_wk2;
    const int nwork = g_nwork[P];

    const uint32_t dsm_raw = smem_u32(dynsmem);
    const uint32_t dsm = (dsm_raw + 127u) & ~127u;

    // ---- prefetch constants (tile-independent) ----
    constexpr int TPR_A = 512 / BM;
    constexpr int APT   = 8 / TPR_A;
    constexpr int TPR_B = 512 / BN;
    constexpr int BPT   = 8 / TPR_B;
    const int  arow  = tid / TPR_A;
    const int  aseg0 = (tid % TPR_A) * APT;
    const uint32_t axm = (uint32_t)((arow & 7) << 4);
    const int  brow  = tid / TPR_B;
    const int  bseg0 = (tid % TPR_B) * BPT;
    const uint32_t bxm = (uint32_t)((brow & 7) << 4);

    // ---- ldmatrix lane constants ----
    const int sel = lane >> 3;
    const uint32_t lxm = (uint32_t)((lane & 7) << 4);
    const uint32_t a_row_off =
        (uint32_t)(wm * 64 + (sel & 1) * 8 + (lane & 7)) * 128;
    const uint32_t a_cs16 = (uint32_t)((sel >> 1) * 16);
    const uint32_t b_row_off =
        (uint32_t)(wn * 32 + (sel >> 1) * 8 + (lane & 7)) * 128;
    const uint32_t b_cs16 = (uint32_t)((sel & 1) * 16);

    while (true) {
        if (tid == 0) sh_wi = atomicAdd(&g_work[P], 1);
        __syncthreads();
        const int wi = sh_wi;
        if (wi >= nwork) break;

        const int enc = wk[wi];
        const int kk = enc >> 16;
        const int row0 = (enc & 0xffff) * BM;
        const int cnt = (kk < 27) ? g_cnt[kk] : N;
        const int* __restrict__ lst = g_list + (size_t)(kk < 27 ? kk : 0) * NPT;

        int id = -1;
        {
            const int gr = row0 + arow;
            if (gr < cnt) id = (kk < 27) ? lst[gr] : gr;
        }
        const int    asz  = (id >= 0) ? 16 : 0;
        const size_t aoff = (size_t)((id >= 0) ? id : 0) * CINL;
        const __half* pbrow = WB + (size_t)brow * KTOT + kk * CINL;

        float acc[4][4][4];
#pragma unroll
        for (int a = 0; a < 4; ++a)
#pragma unroll
            for (int b = 0; b < 4; ++b)
#pragma unroll
                for (int c = 0; c < 4; ++c) acc[a][b][c] = 0.f;

        auto do_prefetch = [&](int c) {
            const int cc = c * 64;
            const uint32_t sb = dsm + (c & 3) * STG;
            const __half* pa = Asrc + aoff + cc + aseg0 * 8;
            const uint32_t da = sb + (uint32_t)arow * 128;
#pragma unroll
            for (int u = 0; u < APT; ++u) {
                const uint32_t so = (uint32_t)((aseg0 + u) * 16) ^ axm;
                cp16(da + so, pa + u * 8, asz);
            }
            const __half* pb = pbrow + cc + bseg0 * 8;
            const uint32_t db = sb + A_BY + (uint32_t)brow * 128;
#pragma unroll
            for (int u = 0; u < BPT; ++u) {
                const uint32_t so = (uint32_t)((bseg0 + u) * 16) ^ bxm;
                cp16(db + so, pb + u * 8, 16);
            }
        };

        do_prefetch(0); CP_COMMIT();
        do_prefetch(1); CP_COMMIT();
        do_prefetch(2); CP_COMMIT();

#pragma unroll 1
        for (int i = 0; i < 7; ++i) {
            CP_WAIT2();
            __syncthreads();
            if (i + 3 < 7) do_prefetch(i + 3);
            CP_COMMIT();

            const uint32_t sb = dsm + (i & 3) * STG;
            const uint32_t aB = sb + a_row_off;
            const uint32_t bB = sb + A_BY + b_row_off;

#pragma unroll
            for (int ks = 0; ks < 4; ++ks) {
                const uint32_t acol = (uint32_t)(ks * 32 + a_cs16) ^ lxm;
                const uint32_t bcol = (uint32_t)(ks * 32 + b_cs16) ^ lxm;
                uint32_t bfr[2][4];
                LDSM_X4(bfr[0][0], bfr[0][1], bfr[0][2], bfr[0][3], bB + bcol);
                LDSM_X4(bfr[1][0], bfr[1][1], bfr[1][2], bfr[1][3], bB + 2048 + bcol);
#pragma unroll
                for (int mt = 0; mt < 4; ++mt) {
                    uint32_t afr[4];
                    LDSM_X4(afr[0], afr[1], afr[2], afr[3], aB + mt * 2048 + acol);
#pragma unroll
                    for (int p = 0; p < 2; ++p) {
                        mma16816(acc[mt][2 * p],     afr, bfr[p][0], bfr[p][1]);
                        mma16816(acc[mt][2 * p + 1], afr, bfr[p][2], bfr[p][3]);
                    }
                }
            }
        }

        // ---- epilogue: coalesced 16B stores in permuted layout ----
#pragma unroll
        for (int mt = 0; mt < 4; ++mt) {
#pragma unroll
            for (int half = 0; half < 2; ++half) {
                const int rl = wm * 64 + mt * 16 + grp + half * 8;
                const int gr = row0 + rl;
                if (gr >= cnt) continue;
                const int j = (kk < 27) ? lst[gr] : gr;
                uint4 v;
                uint32_t* pv = reinterpret_cast<uint32_t*>(&v);
#pragma unroll
                for (int nt = 0; nt < 4; ++nt) {
                    __half2 hv = __floats2half2_rn(acc[mt][nt][half * 2],
                                                   acc[mt][nt][half * 2 + 1]);
                    pv[nt] = *reinterpret_cast<uint32_t*>(&hv);
                }
                *reinterpret_cast<uint4*>(
                    g_G + ((size_t)kk * NPT + j) * GCOLS + wn * 32 + tg * 8) = v;
            }
        }
    }
}

// ---------------- reduce kernels (decode permuted layout) ----------------
__device__ __forceinline__ void acc_u4(float* acc, uint4 v) {
    const __half2* p = reinterpret_cast<const __half2*>(&v);
#pragma unroll
    for (int q = 0; q < 4; ++q) {
        float2 f = __half22float2(p[q]);
        acc[2 * q]     += f.x;
        acc[2 * q + 1] += f.y;
    }
}

__global__ void __launch_bounds__(256)
reduce_zr(const int* __restrict__ nbr, const float* __restrict__ h,
          const float* __restrict__ bz, const float* __restrict__ br, int N) {
    const int i = blockIdx.x * 8 + (threadIdx.x >> 5);
    if (i >= N) return;
    const int lane = threadIdx.x & 31;

    float acc[8];
#pragma unroll
    for (int e = 0; e < 8; ++e) acc[e] = 0.f;

    int idx[27];
    const int* nb = nbr + (size_t)i * 27;
#pragma unroll
    for (int k = 0; k < 27; ++k) idx[k] = nb[k];

    const uint4 z4 = make_uint4(0u, 0u, 0u, 0u);
#pragma unroll 1
    for (int kg = 0; kg < 27; kg += 9) {
        uint4 v[9];
#pragma unroll
        for (int u = 0; u < 9; ++u) {
            const int j = idx[kg + u];
            v[u] = z4;
            if (j >= 0)
                v[u] = __ldg(reinterpret_cast<const uint4*>(
                           g_G + ((size_t)(kg + u) * NPT + j) * 256) + lane);
        }
#pragma unroll
        for (int u = 0; u < 9; ++u) acc_u4(acc, v[u]);
    }
    {
        uint4 v = __ldg(reinterpret_cast<const uint4*>(
                      g_G + ((size_t)27 * NPT + i) * 256) + lane);
        acc_u4(acc, v);
    }

    const int w  = lane >> 2;
    const int tg = lane & 3;
    if (lane < 16) {
#pragma unroll
        for (int t = 0; t < 4; ++t) {
            const int c = w * 32 + t * 8 + tg * 2;
            const float z0 = 1.f / (1.f + __expf(-(acc[2 * t]     + __ldg(&bz[c]))));
            const float z1 = 1.f / (1.f + __expf(-(acc[2 * t + 1] + __ldg(&bz[c + 1]))));
            *reinterpret_cast<float2*>(g_Z + (size_t)i * HID + c) = make_float2(z0, z1);
        }
    } else {
#pragma unroll
        for (int t = 0; t < 4; ++t) {
            const int c = (w - 4) * 32 + t * 8 + tg * 2;
            const float r0 = 1.f / (1.f + __expf(-(acc[2 * t]     + __ldg(&br[c]))));
            const float r1 = 1.f / (1.f + __expf(-(acc[2 * t + 1] + __ldg(&br[c + 1]))));
            const __half2 hv = __floats2half2_rn(r0 * h[(size_t)i * HID + c],
                                                 r1 * h[(size_t)i * HID + c + 1]);
            *reinterpret_cast<__half2*>(g_RX + (size_t)i * CINL + c) = hv;
        }
    }
}

__global__ void __launch_bounds__(256)
reduce_q(const int* __restrict__ nbr, const float* __restrict__ h,
         const float* __restrict__ bq, float* __restrict__ out, int N) {
    const int i = blockIdx.x * 8 + (threadIdx.x >> 5);
    if (i >= N) return;
    const int lane = threadIdx.x & 31;

    float acc[4];
#pragma unroll
    for (int e = 0; e < 4; ++e) acc[e] = 0.f;

    int idx[27];
    const int* nb = nbr + (size_t)i * 27;
#pragma unroll
    for (int k = 0; k < 27; ++k) idx[k] = nb[k];

    const uint2 z2 = make_uint2(0u, 0u);
#pragma unroll 1
    for (int kg = 0; kg < 27; kg += 9) {
        uint2 v[9];
#pragma unroll
        for (int u = 0; u < 9; ++u) {
            const int j = idx[kg + u];
            v[u] = z2;
            if (j >= 0)
                v[u] = __ldg(reinterpret_cast<const uint2*>(
                           g_G + ((size_t)(kg + u) * NPT + j) * 128) + lane);
        }
#pragma unroll
        for (int u = 0; u < 9; ++u) {
            const __half2* p = reinterpret_cast<const __half2*>(&v[u]);
            float2 f0 = __half22float2(p[0]);
            float2 f1 = __half22float2(p[1]);
            acc[0] += f0.x; acc[1] += f0.y; acc[2] += f1.x; acc[3] += f1.y;
        }
    }
    {
        uint2 v = __ldg(reinterpret_cast<const uint2*>(
                      g_G + ((size_t)27 * NPT + i) * 128) + lane);
        const __half2* p = reinterpret_cast<const __half2*>(&v);
        float2 f0 = __half22float2(p[0]);
        float2 f1 = __half22float2(p[1]);
        acc[0] += f0.x; acc[1] += f0.y; acc[2] += f1.x; acc[3] += f1.y;
    }

    const int w   = lane >> 3;
    const int tg  = (lane & 7) >> 1;
    const int nt0 = (lane & 1) * 2;
#pragma unroll
    for (int u = 0; u < 4; ++u) {
        const int c = w * 32 + (nt0 + (u >> 1)) * 8 + tg * 2 + (u & 1);
        const float q  = tanhf(acc[u] + __ldg(&bq[c]));
        const float z  = g_Z[(size_t)i * HID + c];
        const float hv = h[(size_t)i * HID + c];
        out[(size_t)i * HID + c] = fmaf(z, q - hv, hv);
    }
}

// ---------------- launch ----------------
extern "C" void kernel_launch(void* const* d_in, const int* in_sizes, int n_in,
                              void* d_out, int out_size) {
    const float* h     = (const float*)d_in[0];
    const float* x     = (const float*)d_in[1];
    const int*   nbr   = (const int*)  d_in[2];
    const float* Wz    = (const float*)d_in[3];
    const float* Wz_pt = (const float*)d_in[4];
    const float* bz    = (const float*)d_in[5];
    const float* Wr    = (const float*)d_in[6];
    const float* Wr_pt = (const float*)d_in[7];
    const float* br    = (const float*)d_in[8];
    const float* Wq    = (const float*)d_in[9];
    const float* Wq_pt = (const float*)d_in[10];
    const float* bq    = (const float*)d_in[11];

    const int N = in_sizes[0] / HID;
    const int SMEM = 4 * 49152 + 128;   // 196736

    cudaFuncSetAttribute(gemm_G<1, 2, 8>, cudaFuncAttributeMaxDynamicSharedMemorySize, SMEM);
    cudaFuncSetAttribute(gemm_G<2, 4, 4>, cudaFuncAttributeMaxDynamicSharedMemorySize, SMEM);

    int nsm = 148;
    cudaDeviceGetAttribute(&nsm, cudaDevAttrMultiProcessorCount, 0);

    {
        size_t total = (size_t)N * CINL;
        pack_inputs<<<(unsigned)((total + 255) / 256), 256>>>(h, x, N);
    }
    {
        size_t total = (size_t)256 * KTOT;
        pack_wzr<<<(unsigned)((total + 255) / 256), 256>>>(Wz, Wz_pt, Wr, Wr_pt);
    }
    build_lists<<<(N + 255) / 256, 256>>>(nbr, N);
    make_work<<<1, 32>>>(N);

    gemm_G<1, 2, 8><<<nsm, 512, SMEM>>>(N);
    {
        size_t total = (size_t)128 * KTOT;
        pack_wq<<<(unsigned)((total + 255) / 256), 256>>>(Wq, Wq_pt);
    }
    reduce_zr<<<(N + 7) / 8, 256>>>(nbr, h, bz, br, N);
    gemm_G<2, 4, 4><<<nsm, 512, SMEM>>>(N);
    reduce_q<<<(N + 7) / 8, 256>>>(nbr, h, bq, (float*)d_out, N);
}

// round 15
// speedup vs baseline: 1.0168x; 1.0168x over previous
#include <cuda_runtime.h>
#include <cuda_fp16.h>
#include <cstdint>

#define NPT   120000
#define HID   128
#define INP   320
#define CINL  448
#define KOFF  28
#define KTOT  (KOFF * CINL)     // 12544

// ---------------- device scratch ----------------
__device__ __half g_HX [(size_t)NPT * CINL];
__device__ __half g_RX [(size_t)NPT * CINL];
__device__ float  g_Z  [(size_t)NPT * HID];
__device__ __half g_Wzr[(size_t)256 * KTOT];   // [n][k*448+c]  n<128: z, n>=128: r
__device__ __half g_Wq [(size_t)128 * KTOT];   // [n][k*448+c]
// G buffer, PERMUTED column layout within each 32-col warp chunk:
//   storage half index within chunk = tg*8 + nt*2 + e  (chunk w at halves w*32)
__device__ __half g_G  [(size_t)KOFF * NPT * 256];
__device__ int    g_list[(size_t)27 * NPT];
__device__ int    g_cnt[27];

// ---------------- asm helpers ----------------
__device__ __forceinline__ uint32_t smem_u32(const void* p) {
    uint32_t a;
    asm("{ .reg .u64 t; cvta.to.shared.u64 t, %1; cvt.u32.u64 %0, t; }" : "=r"(a) : "l"(p));
    return a;
}
__device__ __forceinline__ void cp16(uint32_t dst, const void* src, int sz) {
    asm volatile("cp.async.cg.shared.global [%0], [%1], 16, %2;"
                 :: "r"(dst), "l"(src), "r"(sz) : "memory");
}
#define CP_COMMIT() asm volatile("cp.async.commit_group;" ::: "memory")
#define CP_WAIT2()  asm volatile("cp.async.wait_group 2;" ::: "memory")

#define LDSM_X4(r0, r1, r2, r3, addr) \
    asm volatile("ldmatrix.sync.aligned.m8n8.x4.shared.b16 {%0,%1,%2,%3}, [%4];" \
        : "=r"(r0), "=r"(r1), "=r"(r2), "=r"(r3) : "r"(addr))

__device__ __forceinline__ void mma16816(float* d, const uint32_t* a, uint32_t b0, uint32_t b1) {
    asm volatile(
        "mma.sync.aligned.m16n8k16.row.col.f32.f16.f16.f32 "
        "{%0,%1,%2,%3}, {%4,%5,%6,%7}, {%8,%9}, {%0,%1,%2,%3};"
        : "+f"(d[0]), "+f"(d[1]), "+f"(d[2]), "+f"(d[3])
        : "r"(a[0]), "r"(a[1]), "r"(a[2]), "r"(a[3]), "r"(b0), "r"(b1));
}

// ---------------- small kernels ----------------
__global__ void pack_inputs(const float* __restrict__ h, const float* __restrict__ x, int N) {
    if (blockIdx.x == 0 && threadIdx.x < 27) g_cnt[threadIdx.x] = 0;
    size_t idx = (size_t)blockIdx.x * blockDim.x + threadIdx.x;
    size_t total = (size_t)N * CINL;
    if (idx >= total) return;
    int c = (int)(idx % CINL);
    size_t n = idx / CINL;
    float v = (c < HID) ? h[n * HID + c] : x[n * INP + (c - HID)];
    __half hv = __float2half_rn(v);
    g_HX[idx] = hv;
    if (c >= HID) g_RX[idx] = hv;
}

// single tiled-transpose weight pack: coalesced reads AND writes.
// grid (14, 12, 28): x = c-tile (448/32), y = n-plane (0-3 z, 4-7 r, 8-11 q), z = k
__global__ void __launch_bounds__(256)
pack_W(const float* __restrict__ Wz, const float* __restrict__ Wz_pt,
       const float* __restrict__ Wr, const float* __restrict__ Wr_pt,
       const float* __restrict__ Wq, const float* __restrict__ Wq_pt) {
    __shared__ float tile[32][33];
    const int k  = blockIdx.z;
    const int c0 = blockIdx.x * 32;
    const int nt = blockIdx.y;
    const int n0 = (nt & 3) * 32;
    const float* src;
    if (nt < 4)      src = (k < 27) ? Wz + (size_t)k * CINL * HID : Wz_pt;
    else if (nt < 8) src = (k < 27) ? Wr + (size_t)k * CINL * HID : Wr_pt;
    else             src = (k < 27) ? Wq + (size_t)k * CINL * HID : Wq_pt;

    const int tx = threadIdx.x;       // 0..31
    const int ty = threadIdx.y;       // 0..7
#pragma unroll
    for (int i = ty; i < 32; i += 8)
        tile[i][tx] = src[(size_t)(c0 + i) * HID + n0 + tx];
    __syncthreads();
#pragma unroll
    for (int i = ty; i < 32; i += 8) {
        const int n = n0 + i;
        const __half hv = __float2half_rn(tile[tx][i]);
        if (nt < 8) {
            const int row = (nt < 4) ? n : n + 128;
            g_Wzr[(size_t)row * KTOT + (size_t)k * CINL + c0 + tx] = hv;
        } else {
            g_Wq[(size_t)n * KTOT + (size_t)k * CINL + c0 + tx] = hv;
        }
    }
}

// build per-k lists of rows j that are read as k-neighbors:
// G[k][j] is needed  <=>  nbr[j][26-k] >= 0   (mirror symmetry)
__global__ void build_lists(const int* __restrict__ nbr, int N) {
    const int j = blockIdx.x * blockDim.x + threadIdx.x;
    const int lane = threadIdx.x & 31;
    const bool inb = (j < N);
#pragma unroll 1
    for (int k = 0; k < 27; ++k) {
        bool v = inb && (nbr[(size_t)j * 27 + (26 - k)] >= 0);
        unsigned m = __ballot_sync(0xffffffffu, v);
        int base = 0;
        if (lane == 0 && m) base = atomicAdd(&g_cnt[k], __popc(m));
        base = __shfl_sync(0xffffffffu, base, 0);
        if (v) g_list[(size_t)k * NPT + base + __popc(m & ((1u << lane) - 1u))] = j;
    }
}

// ---------------- G GEMM kernel ----------------
// For each k (0..26: compacted valid rows; 27: identity/pt slot):
//   PASS 1: G[k][j][0:256] = HX[j] @ Wzr[k]   BM=128 (WM=2) x BN=256 (WN=8)
//   PASS 2: G[k][j][0:128] = RX[j] @ Wq[k]    BM=256 (WM=4) x BN=128 (WN=4)
// Epilogue: coalesced 16B stores in permuted G layout.
template <int PASS, int WM, int WN>
__global__ void __launch_bounds__(512, 1)
gemm_G(int N) {
    constexpr int BM = WM * 64;
    constexpr int BN = WN * 32;
    constexpr int A_BY = BM * 128;
    constexpr int B_BY = BN * 128;
    constexpr int STG = A_BY + B_BY;          // 49152 both
    constexpr int NTILE = (NPT + BM - 1) / BM;
    constexpr int GCOLS = (PASS == 1) ? 256 : 128;

    const int kk = blockIdx.x / NTILE;        // 0..27
    const int t  = blockIdx.x % NTILE;
    const int row0 = t * BM;

    const int cnt = (kk < 27) ? g_cnt[kk] : N;
    if (row0 >= cnt) return;

    extern __shared__ __align__(128) char dynsmem[];

    const int tid  = threadIdx.x;
    const int wid  = tid >> 5;
    const int lane = tid & 31;
    const int wm   = wid / WN;
    const int wn   = wid % WN;
    const int grp  = lane >> 2;
    const int tg   = lane & 3;

    const __half* __restrict__ Asrc = (PASS == 1) ? g_HX : g_RX;
    const __half* __restrict__ WB   = (PASS == 1) ? g_Wzr : g_Wq;
    const int* __restrict__ lst = g_list + (size_t)(kk < 27 ? kk : 0) * NPT;

    const uint32_t dsm_raw = smem_u32(dynsmem);
    const uint32_t dsm = (dsm_raw + 127u) & ~127u;

    // ---- prefetch constants ----
    constexpr int TPR_A = 512 / BM;
    constexpr int APT   = 8 / TPR_A;
    constexpr int TPR_B = 512 / BN;
    constexpr int BPT   = 8 / TPR_B;
    const int  arow  = tid / TPR_A;
    const int  aseg0 = (tid % TPR_A) * APT;
    const uint32_t axm = (uint32_t)((arow & 7) << 4);
    const int  brow  = tid / TPR_B;
    const int  bseg0 = (tid % TPR_B) * BPT;
    const uint32_t bxm = (uint32_t)((brow & 7) << 4);

    int id = -1;
    {
        const int gr = row0 + arow;
        if (gr < cnt) id = (kk < 27) ? lst[gr] : gr;
    }
    const int    asz  = (id >= 0) ? 16 : 0;
    const size_t aoff = (size_t)((id >= 0) ? id : 0) * CINL;
    const __half* pbrow = WB + (size_t)brow * KTOT + kk * CINL;

    // ---- ldmatrix lane constants ----
    const int sel = lane >> 3;
    const uint32_t lxm = (uint32_t)((lane & 7) << 4);
    const uint32_t a_row_off =
        (uint32_t)(wm * 64 + (sel & 1) * 8 + (lane & 7)) * 128;
    const uint32_t a_cs16 = (uint32_t)((sel >> 1) * 16);
    const uint32_t b_row_off =
        (uint32_t)(wn * 32 + (sel >> 1) * 8 + (lane & 7)) * 128;
    const uint32_t b_cs16 = (uint32_t)((sel & 1) * 16);

    float acc[4][4][4];
#pragma unroll
    for (int a = 0; a < 4; ++a)
#pragma unroll
        for (int b = 0; b < 4; ++b)
#pragma unroll
            for (int c = 0; c < 4; ++c) acc[a][b][c] = 0.f;

    auto do_prefetch = [&](int c) {
        const int cc = c * 64;
        const uint32_t sb = dsm + (c & 3) * STG;
        const __half* pa = Asrc + aoff + cc + aseg0 * 8;
        const uint32_t da = sb + (uint32_t)arow * 128;
#pragma unroll
        for (int u = 0; u < APT; ++u) {
            const uint32_t so = (uint32_t)((aseg0 + u) * 16) ^ axm;
            cp16(da + so, pa + u * 8, asz);
        }
        const __half* pb = pbrow + cc + bseg0 * 8;
        const uint32_t db = sb + A_BY + (uint32_t)brow * 128;
#pragma unroll
        for (int u = 0; u < BPT; ++u) {
            const uint32_t so = (uint32_t)((bseg0 + u) * 16) ^ bxm;
            cp16(db + so, pb + u * 8, 16);
        }
    };

    do_prefetch(0); CP_COMMIT();
    do_prefetch(1); CP_COMMIT();
    do_prefetch(2); CP_COMMIT();

#pragma unroll 1
    for (int i = 0; i < 7; ++i) {
        CP_WAIT2();
        __syncthreads();
        if (i + 3 < 7) do_prefetch(i + 3);
        CP_COMMIT();

        const uint32_t sb = dsm + (i & 3) * STG;
        const uint32_t aB = sb + a_row_off;
        const uint32_t bB = sb + A_BY + b_row_off;

#pragma unroll
        for (int ks = 0; ks < 4; ++ks) {
            const uint32_t acol = (uint32_t)(ks * 32 + a_cs16) ^ lxm;
            const uint32_t bcol = (uint32_t)(ks * 32 + b_cs16) ^ lxm;
            uint32_t bfr[2][4];
            LDSM_X4(bfr[0][0], bfr[0][1], bfr[0][2], bfr[0][3], bB + bcol);
            LDSM_X4(bfr[1][0], bfr[1][1], bfr[1][2], bfr[1][3], bB + 2048 + bcol);
#pragma unroll
            for (int mt = 0; mt < 4; ++mt) {
                uint32_t afr[4];
                LDSM_X4(afr[0], afr[1], afr[2], afr[3], aB + mt * 2048 + acol);
#pragma unroll
                for (int p = 0; p < 2; ++p) {
                    mma16816(acc[mt][2 * p],     afr, bfr[p][0], bfr[p][1]);
                    mma16816(acc[mt][2 * p + 1], afr, bfr[p][2], bfr[p][3]);
                }
            }
        }
    }

    // ---- epilogue: coalesced 16B stores in permuted layout ----
#pragma unroll
    for (int mt = 0; mt < 4; ++mt) {
#pragma unroll
        for (int half = 0; half < 2; ++half) {
            const int rl = wm * 64 + mt * 16 + grp + half * 8;
            const int gr = row0 + rl;
            if (gr >= cnt) continue;
            const int j = (kk < 27) ? lst[gr] : gr;
            uint4 v;
            uint32_t* pv = reinterpret_cast<uint32_t*>(&v);
#pragma unroll
            for (int nt = 0; nt < 4; ++nt) {
                __half2 hv = __floats2half2_rn(acc[mt][nt][half * 2],
                                               acc[mt][nt][half * 2 + 1]);
                pv[nt] = *reinterpret_cast<uint32_t*>(&hv);
            }
            *reinterpret_cast<uint4*>(
                g_G + ((size_t)kk * NPT + j) * GCOLS + wn * 32 + tg * 8) = v;
        }
    }
}

// ---------------- reduce kernels (decode permuted layout) ----------------
__device__ __forceinline__ void acc_u4(float* acc, uint4 v) {
    const __half2* p = reinterpret_cast<const __half2*>(&v);
#pragma unroll
    for (int q = 0; q < 4; ++q) {
        float2 f = __half22float2(p[q]);
        acc[2 * q]     += f.x;
        acc[2 * q + 1] += f.y;
    }
}

__global__ void __launch_bounds__(256)
reduce_zr(const int* __restrict__ nbr, const float* __restrict__ h,
          const float* __restrict__ bz, const float* __restrict__ br, int N) {
    const int i = blockIdx.x * 8 + (threadIdx.x >> 5);
    if (i >= N) return;
    const int lane = threadIdx.x & 31;

    float acc[8];
#pragma unroll
    for (int e = 0; e < 8; ++e) acc[e] = 0.f;

    int idx[27];
    const int* nb = nbr + (size_t)i * 27;
#pragma unroll
    for (int k = 0; k < 27; ++k) idx[k] = nb[k];

    const uint4 z4 = make_uint4(0u, 0u, 0u, 0u);
#pragma unroll 1
    for (int kg = 0; kg < 27; kg += 9) {
        uint4 v[9];
#pragma unroll
        for (int u = 0; u < 9; ++u) {
            const int j = idx[kg + u];
            v[u] = z4;
            if (j >= 0)
                v[u] = __ldg(reinterpret_cast<const uint4*>(
                           g_G + ((size_t)(kg + u) * NPT + j) * 256) + lane);
        }
#pragma unroll
        for (int u = 0; u < 9; ++u) acc_u4(acc, v[u]);
    }
    {
        uint4 v = __ldg(reinterpret_cast<const uint4*>(
                      g_G + ((size_t)27 * NPT + i) * 256) + lane);
        acc_u4(acc, v);
    }

    const int w  = lane >> 2;
    const int tg = lane & 3;
    if (lane < 16) {
#pragma unroll
        for (int t = 0; t < 4; ++t) {
            const int c = w * 32 + t * 8 + tg * 2;
            const float z0 = 1.f / (1.f + __expf(-(acc[2 * t]     + __ldg(&bz[c]))));
            const float z1 = 1.f / (1.f + __expf(-(acc[2 * t + 1] + __ldg(&bz[c + 1]))));
            *reinterpret_cast<float2*>(g_Z + (size_t)i * HID + c) = make_float2(z0, z1);
        }
    } else {
#pragma unroll
        for (int t = 0; t < 4; ++t) {
            const int c = (w - 4) * 32 + t * 8 + tg * 2;
            const float r0 = 1.f / (1.f + __expf(-(acc[2 * t]     + __ldg(&br[c]))));
            const float r1 = 1.f / (1.f + __expf(-(acc[2 * t + 1] + __ldg(&br[c + 1]))));
            const __half2 hv = __floats2half2_rn(r0 * h[(size_t)i * HID + c],
                                                 r1 * h[(size_t)i * HID + c + 1]);
            *reinterpret_cast<__half2*>(g_RX + (size_t)i * CINL + c) = hv;
        }
    }
}

__global__ void __launch_bounds__(256)
reduce_q(const int* __restrict__ nbr, const float* __restrict__ h,
         const float* __restrict__ bq, float* __restrict__ out, int N) {
    const int i = blockIdx.x * 8 + (threadIdx.x >> 5);
    if (i >= N) return;
    const int lane = threadIdx.x & 31;

    float acc[4];
#pragma unroll
    for (int e = 0; e < 4; ++e) acc[e] = 0.f;

    int idx[27];
    const int* nb = nbr + (size_t)i * 27;
#pragma unroll
    for (int k = 0; k < 27; ++k) idx[k] = nb[k];

    const uint2 z2 = make_uint2(0u, 0u);
#pragma unroll 1
    for (int kg = 0; kg < 27; kg += 9) {
        uint2 v[9];
#pragma unroll
        for (int u = 0; u < 9; ++u) {
            const int j = idx[kg + u];
            v[u] = z2;
            if (j >= 0)
                v[u] = __ldg(reinterpret_cast<const uint2*>(
                           g_G + ((size_t)(kg + u) * NPT + j) * 128) + lane);
        }
#pragma unroll
        for (int u = 0; u < 9; ++u) {
            const __half2* p = reinterpret_cast<const __half2*>(&v[u]);
            float2 f0 = __half22float2(p[0]);
            float2 f1 = __half22float2(p[1]);
            acc[0] += f0.x; acc[1] += f0.y; acc[2] += f1.x; acc[3] += f1.y;
        }
    }
    {
        uint2 v = __ldg(reinterpret_cast<const uint2*>(
                      g_G + ((size_t)27 * NPT + i) * 128) + lane);
        const __half2* p = reinterpret_cast<const __half2*>(&v);
        float2 f0 = __half22float2(p[0]);
        float2 f1 = __half22float2(p[1]);
        acc[0] += f0.x; acc[1] += f0.y; acc[2] += f1.x; acc[3] += f1.y;
    }

    const int w   = lane >> 3;
    const int tg  = (lane & 7) >> 1;
    const int nt0 = (lane & 1) * 2;
#pragma unroll
    for (int u = 0; u < 4; ++u) {
        const int c = w * 32 + (nt0 + (u >> 1)) * 8 + tg * 2 + (u & 1);
        const float q  = tanhf(acc[u] + __ldg(&bq[c]));
        const float z  = g_Z[(size_t)i * HID + c];
        const float hv = h[(size_t)i * HID + c];
        out[(size_t)i * HID + c] = fmaf(z, q - hv, hv);
    }
}

// ---------------- launch ----------------
extern "C" void kernel_launch(void* const* d_in, const int* in_sizes, int n_in,
                              void* d_out, int out_size) {
    const float* h     = (const float*)d_in[0];
    const float* x     = (const float*)d_in[1];
    const int*   nbr   = (const int*)  d_in[2];
    const float* Wz    = (const float*)d_in[3];
    const float* Wz_pt = (const float*)d_in[4];
    const float* bz    = (const float*)d_in[5];
    const float* Wr    = (const float*)d_in[6];
    const float* Wr_pt = (const float*)d_in[7];
    const float* br    = (const float*)d_in[8];
    const float* Wq    = (const float*)d_in[9];
    const float* Wq_pt = (const float*)d_in[10];
    const float* bq    = (const float*)d_in[11];

    const int N = in_sizes[0] / HID;
    const int SMEM = 4 * 49152 + 128;   // 196736

    cudaFuncSetAttribute(gemm_G<1, 2, 8>, cudaFuncAttributeMaxDynamicSharedMemorySize, SMEM);
    cudaFuncSetAttribute(gemm_G<2, 4, 4>, cudaFuncAttributeMaxDynamicSharedMemorySize, SMEM);

    {
        size_t total = (size_t)N * CINL;
        pack_inputs<<<(unsigned)((total + 255) / 256), 256>>>(h, x, N);
    }
    {
        dim3 g(14, 12, 28);
        dim3 b(32, 8);
        pack_W<<<g, b>>>(Wz, Wz_pt, Wr, Wr_pt, Wq, Wq_pt);
    }
    build_lists<<<(N + 255) / 256, 256>>>(nbr, N);

    constexpr int NTILE1 = (NPT + 127) / 128;   // 938
    constexpr int NTILE2 = (NPT + 255) / 256;   // 469

    gemm_G<1, 2, 8><<<28 * NTILE1, 512, SMEM>>>(N);
    reduce_zr<<<(N + 7) / 8, 256>>>(nbr, h, bz, br, N);
    gemm_G<2, 4, 4><<<28 * NTILE2, 512, SMEM>>>(N);
    reduce_q<<<(N + 7) / 8, 256>>>(nbr, h, bq, (float*)d_out, N);
}